// round 6
// baseline (speedup 1.0000x reference)
#include <cuda_runtime.h>
#include <cstdint>
#include <cstddef>

// ---------------------------------------------------------------------------
// GAT layer (sm_103, mma.sync tf32). R4:
//  - adj pre-packed to bitmask (8MB, L2-resident) by gat_kp
//  - k2: 512 threads (16 warps, 4x4 tiling), BK=32, 128 chunks, B-only cp.async
//  - exp-free inner loop via piecewise factorization (R3)
// ---------------------------------------------------------------------------

static __device__ __forceinline__ uint32_t smem_u32(const void* p) {
    uint32_t a;
    asm("{ .reg .u64 t; cvta.to.shared.u64 t, %1; cvt.u32.u64 %0, t; }" : "=r"(a) : "l"(p));
    return a;
}
static __device__ __forceinline__ uint32_t f32_tf32(float x) {
    uint32_t r; asm("cvt.rna.tf32.f32 %0, %1;" : "=r"(r) : "f"(x)); return r;
}

#define CPA16(dst, src) asm volatile("cp.async.cg.shared.global [%0], [%1], 16;" :: "r"(dst), "l"(src) : "memory")
#define CPA_COMMIT()    asm volatile("cp.async.commit_group;" ::: "memory")
#define CPA_WAIT(n)     asm volatile("cp.async.wait_group %0;" :: "n"(n) : "memory")

static __device__ __forceinline__ void mma8(float* c, const uint32_t* a, const uint32_t* b) {
    asm volatile(
        "mma.sync.aligned.m16n8k8.row.col.f32.tf32.tf32.f32 "
        "{%0,%1,%2,%3},{%4,%5,%6,%7},{%8,%9},{%0,%1,%2,%3};"
        : "+f"(c[0]), "+f"(c[1]), "+f"(c[2]), "+f"(c[3])
        : "r"(a[0]), "r"(a[1]), "r"(a[2]), "r"(a[3]), "r"(b[0]), "r"(b[1]));
}

static __device__ __forceinline__ unsigned int enc_f(float f) {
    unsigned int b = __float_as_uint(f);
    return (b & 0x80000000u) ? ~b : (b | 0x80000000u);
}
static __device__ __forceinline__ float dec_f(unsigned int u) {
    return (u & 0x80000000u) ? __uint_as_float(u & 0x7FFFFFFFu) : __uint_as_float(~u);
}

// permuted-16: element k of a 16-block stored at (k&3)*4 + (k>>2)
static __device__ __forceinline__ int perm16(int i) {
    return (i & ~15) + ((i & 3) << 2) + ((i >> 2) & 3);
}

// ------------------------- scratch (device globals) -------------------------
__device__ __align__(16) uint32_t g_WT2[256 * 512];    // tf32 W^T, perm16 over k
__device__ __align__(16) uint32_t g_WhT2[256 * 8192];  // tf32 Wh^T, perm16 over i
__device__ __align__(16) uint32_t g_adjb[8192 * 256];  // adj bitmask, 32 j per word
__device__ __align__(16) float    g_wa[1024];          // [2][512]
__device__ __align__(16) float    g_f1[8192];
__device__ __align__(16) float    g_f2[8192];
__device__ unsigned int           g_f2max;
__device__ __align__(16) float2   g_v[8192];           // (v_j, vh_j)
__device__ __align__(16) float    g_part[2][8192 * 256];
__device__ __align__(16) float    g_lpart[2][8192];

// ------------------------------- kernel p ----------------------------------
// pack adj -> bits. 2M threads, each 32 consecutive ints -> 1 word.
__global__ void gat_kp(const int* __restrict__ adj) {
    int t = blockIdx.x * 256 + threadIdx.x;           // 0..2097151
    const int4* p = (const int4*)(adj + (size_t)t * 32);
    uint32_t bits = 0;
#pragma unroll
    for (int q = 0; q < 8; q++) {
        int4 v = p[q];
        bits |= (v.x > 0 ? 1u : 0u) << (4 * q)
             |  (v.y > 0 ? 1u : 0u) << (4 * q + 1)
             |  (v.z > 0 ? 1u : 0u) << (4 * q + 2)
             |  (v.w > 0 ? 1u : 0u) << (4 * q + 3);
    }
    g_adjb[t] = bits;
}

// ------------------------------- kernel 0 ----------------------------------
__global__ void gat_k0(const float* __restrict__ W) {
    int idx = blockIdx.x * 256 + threadIdx.x;  // 0..131071
    int n = idx >> 9, k = idx & 511;
    g_WT2[n * 512 + perm16(k)] = f32_tf32(W[k * 256 + n]);
    if (idx == 0) g_f2max = 0u;
}

__global__ void gat_k0b(const float* __restrict__ W, const float* __restrict__ a) {
    int idx = blockIdx.x * 256 + threadIdx.x;  // 0..1023
    int which = idx >> 9, kk = idx & 511;
    const float* wrow = W + kk * 256;
    const float* ap = a + which * 256;
    float s = 0.f;
    for (int n = 0; n < 256; n++) s += wrow[n] * ap[n];
    g_wa[idx] = s;
}

__global__ void gat_kf(const float* __restrict__ h) {
    __shared__ float swa[1024];
    int tid = threadIdx.x, wid = tid >> 5, lane = tid & 31;
    for (int i = tid; i < 1024; i += 256) swa[i] = g_wa[i];
    __syncthreads();
    int row = blockIdx.x * 8 + wid;
    const float* hr = h + (size_t)row * 512;
    float s1 = 0.f, s2 = 0.f;
    for (int kk = lane; kk < 512; kk += 32) {
        float v = hr[kk];
        s1 += v * swa[kk];
        s2 += v * swa[512 + kk];
    }
#pragma unroll
    for (int o = 16; o > 0; o >>= 1) {
        s1 += __shfl_down_sync(0xFFFFFFFFu, s1, o);
        s2 += __shfl_down_sync(0xFFFFFFFFu, s2, o);
    }
    if (lane == 0) {
        g_f1[row] = s1;
        g_f2[row] = s2;
        atomicMax(&g_f2max, enc_f(s2));
    }
}

__global__ void gat_kv() {
    int j = blockIdx.x * 256 + threadIdx.x;
    float d = g_f2[j] - dec_f(g_f2max);
    g_v[j] = make_float2(__expf(d), __expf(0.2f * d));
}

// ------------------------------- kernel 1 ----------------------------------
// Wh GEMM: grid 128 (BM=64), BN=256, BK=16, depth-2 cp.async.
__global__ void __launch_bounds__(256, 1) gat_k1(const float* __restrict__ h) {
    extern __shared__ float sm[];
    float* As = sm;
    float* Bs = sm + 3840;

    int tid = threadIdx.x, wid = tid >> 5, lane = tid & 31;
    int wm = wid & 1, wn = wid >> 1;
    int r0 = blockIdx.x * 64;
    int arow = tid >> 2, aq = tid & 3;
    const float* hsrc = h + (size_t)(r0 + arow) * 512 + aq * 4;
    const uint32_t* bsrc = g_WT2 + (size_t)tid * 512;

    float c[2][8][4];
#pragma unroll
    for (int mt = 0; mt < 2; mt++)
#pragma unroll
        for (int nt = 0; nt < 8; nt++)
#pragma unroll
            for (int q = 0; q < 4; q++) c[mt][nt][q] = 0.f;

    auto prefetch = [&](int ch) {
        int b = ch % 3, k0c = ch * 16;
        CPA16(smem_u32(As + b * 1280 + arow * 20 + aq * 4), hsrc + k0c);
        uint32_t bd = smem_u32(Bs + b * 4096 + tid * 16);
        const uint32_t* bp = bsrc + k0c;
        CPA16(bd, bp); CPA16(bd + 16, bp + 4);
        CPA16(bd + 32, bp + 8); CPA16(bd + 48, bp + 12);
    };

    prefetch(0); CPA_COMMIT();
    prefetch(1); CPA_COMMIT();
    CPA_WAIT(1);

    for (int ch = 0; ch < 32; ch++) {
        __syncthreads();
        if (ch + 2 < 32) { prefetch(ch + 2); CPA_COMMIT(); CPA_WAIT(1); }
        else CPA_WAIT(0);
        int b = ch % 3;
        const float4* Bb = (const float4*)(Bs + b * 4096);
        const float* Ab = As + b * 1280;
        float4 bv[8];
#pragma unroll
        for (int nt = 0; nt < 8; nt++)
            bv[nt] = Bb[(wn * 64 + nt * 8 + (lane >> 2)) * 4 + (lane & 3)];
#pragma unroll
        for (int mt = 0; mt < 2; mt++) {
            int rl = wm * 32 + mt * 16 + (lane >> 2);
            int cc = lane & 3;
#pragma unroll
            for (int s = 0; s < 2; s++) {
                uint32_t af[4];
                af[0] = *(const uint32_t*)(Ab + rl * 20 + s * 8 + cc);
                af[1] = *(const uint32_t*)(Ab + (rl + 8) * 20 + s * 8 + cc);
                af[2] = *(const uint32_t*)(Ab + rl * 20 + s * 8 + cc + 4);
                af[3] = *(const uint32_t*)(Ab + (rl + 8) * 20 + s * 8 + cc + 4);
#pragma unroll
                for (int nt = 0; nt < 8; nt++) {
                    uint32_t bf[2];
                    if (s == 0) { bf[0] = __float_as_uint(bv[nt].x); bf[1] = __float_as_uint(bv[nt].y); }
                    else        { bf[0] = __float_as_uint(bv[nt].z); bf[1] = __float_as_uint(bv[nt].w); }
                    mma8(c[mt][nt], af, bf);
                }
            }
        }
    }

#pragma unroll
    for (int mt = 0; mt < 2; mt++) {
        int i = r0 + wm * 32 + mt * 16 + (lane >> 2);
#pragma unroll
        for (int nt = 0; nt < 8; nt++) {
            int n = wn * 64 + nt * 8 + (lane & 3) * 2;
            g_WhT2[(size_t)n * 8192 + perm16(i)]           = f32_tf32(c[mt][nt][0]);
            g_WhT2[(size_t)(n + 1) * 8192 + perm16(i)]     = f32_tf32(c[mt][nt][1]);
            g_WhT2[(size_t)n * 8192 + perm16(i + 8)]       = f32_tf32(c[mt][nt][2]);
            g_WhT2[(size_t)(n + 1) * 8192 + perm16(i + 8)] = f32_tf32(c[mt][nt][3]);
        }
    }
}

// ------------------------------- kernel 2 ----------------------------------
// Fused attention GEMM. grid 128 = 64 rowblocks x split-j2, 512 threads,
// BM=128, BN=256, BK=32, 128 chunks. adj via bitmask LDG; cp.async = B only.
// SMEM floats: Vs(float2)[4096] @0 (8192f) | A2 2*4096 @8192 | B2 3*8192 @16384
//   total 40960 f = 163840 B
__global__ void __launch_bounds__(512, 1) gat_k2() {
    extern __shared__ float sm[];
    float2* Vs = (float2*)sm;        // [4096]
    float* A2 = sm + 8192;           // [2][128*32]
    float* B2 = sm + 16384;          // [3][256*32]

    int tid = threadIdx.x, wid = tid >> 5, lane = tid & 31;
    int wm = wid & 3, wn = wid >> 2;             // 4x4 warp grid
    int rb = blockIdx.x & 63, sp = blockIdx.x >> 6;
    int r0 = rb * 128;
    int jbase = sp * 4096;
    int prow = tid >> 2, q = tid & 3;            // P producer mapping
    int bn = tid >> 1, bkh = tid & 1;            // B loader mapping

    for (int i = tid; i < 4096; i += 512) Vs[i] = g_v[jbase + i];

    float f2m = dec_f(g_f2max);
    float f1r = g_f1[r0 + prow];
    float tb = f1r + f2m;
    float m_r = fmaxf(tb, 0.2f * tb);
    float u   = __expf(tb - m_r);
    float uh  = __expf(0.2f * tb - m_r);
    float thr = __expf(-tb);   // v_j >= thr  <=>  f1r + f2_j >= 0
    float l_acc = 0.f;

    const uint32_t* abits = g_adjb + (size_t)(r0 + prow) * 256 + sp * 128;
    const uint32_t* bsrc = g_WhT2 + (size_t)bn * 8192 + jbase + bkh * 16;

    float c[2][8][4];
#pragma unroll
    for (int mt = 0; mt < 2; mt++)
#pragma unroll
        for (int nt = 0; nt < 8; nt++)
#pragma unroll
            for (int qq = 0; qq < 4; qq++) c[mt][nt][qq] = 0.f;

    auto prefetch = [&](int ch) {
        int b = ch % 3;
        uint32_t bd = smem_u32(B2 + b * 8192 + bn * 32 + bkh * 16);
        const uint32_t* bp = bsrc + ch * 32;
        CPA16(bd, bp); CPA16(bd + 16, bp + 4);
        CPA16(bd + 32, bp + 8); CPA16(bd + 48, bp + 12);
    };

    auto compute = [&](int ch) {  // P(ch) -> A2[ch&1], fragment-permuted
        uint32_t w = __ldg(abits + ch);
        const float2* vs = Vs + ch * 32;
        float* dst = A2 + (ch & 1) * 4096 + prow * 32 + q * 4;
#pragma unroll
        for (int kb = 0; kb < 2; kb++) {
            float pv[4];
#pragma unroll
            for (int kq = 0; kq < 4; kq++) {
                int j = kb * 16 + q + 4 * kq;
                float2 v2 = vs[j];
                float sv = (v2.x >= thr) ? v2.x : v2.y;
                float su = (v2.x >= thr) ? u : uh;
                float p = ((w >> j) & 1u) ? su * sv : 0.f;
                p = __uint_as_float(f32_tf32(p));
                l_acc += p;
                pv[kq] = p;
            }
            *(float4*)(dst + kb * 16) = make_float4(pv[0], pv[1], pv[2], pv[3]);
        }
    };

    prefetch(0); CPA_COMMIT();
    prefetch(1); CPA_COMMIT();
    CPA_WAIT(1);
    __syncthreads();
    compute(0);

    for (int ch = 0; ch < 128; ch++) {
        __syncthreads();  // publishes A2[ch&1]; all warps past mma(ch-1)
        if (ch + 1 < 128) compute(ch + 1);
        if (ch + 2 < 128) { prefetch(ch + 2); CPA_COMMIT(); CPA_WAIT(1); }
        else CPA_WAIT(0);

        int b = ch % 3, ab = ch & 1;
        const float* Bb = B2 + b * 8192;
        const float* Aa = A2 + ab * 4096;
        int cc = lane & 3, rr = lane >> 2;
#pragma unroll
        for (int kb = 0; kb < 2; kb++) {
            float4 bv[8];
#pragma unroll
            for (int nt = 0; nt < 8; nt++)
                bv[nt] = *(const float4*)(Bb + (wn * 64 + nt * 8 + rr) * 32 + kb * 16 + cc * 4);
#pragma unroll
            for (int mt = 0; mt < 2; mt++) {
                int rl = wm * 32 + mt * 16 + rr;
                float4 lo = *(const float4*)(Aa + rl * 32 + kb * 16 + cc * 4);
                float4 hi = *(const float4*)(Aa + (rl + 8) * 32 + kb * 16 + cc * 4);
                uint32_t a0[4] = {__float_as_uint(lo.x), __float_as_uint(hi.x),
                                  __float_as_uint(lo.y), __float_as_uint(hi.y)};
                uint32_t a1[4] = {__float_as_uint(lo.z), __float_as_uint(hi.z),
                                  __float_as_uint(lo.w), __float_as_uint(hi.w)};
#pragma unroll
                for (int nt = 0; nt < 8; nt++) {
                    uint32_t b0[2] = {__float_as_uint(bv[nt].x), __float_as_uint(bv[nt].y)};
                    mma8(c[mt][nt], a0, b0);
                    uint32_t b1[2] = {__float_as_uint(bv[nt].z), __float_as_uint(bv[nt].w)};
                    mma8(c[mt][nt], a1, b1);
                }
            }
        }
    }

    // l: sum across the 4 producer threads of each row (consecutive lanes)
    float lt = l_acc + __shfl_xor_sync(0xFFFFFFFFu, l_acc, 1);
    lt += __shfl_xor_sync(0xFFFFFFFFu, lt, 2);
    if (q == 0) g_lpart[sp][r0 + prow] = lt;

#pragma unroll
    for (int mt = 0; mt < 2; mt++) {
        int i = r0 + wm * 32 + mt * 16 + (lane >> 2);
#pragma unroll
        for (int nt = 0; nt < 8; nt++) {
            int n = wn * 64 + nt * 8 + (lane & 3) * 2;
            float2 lo = make_float2(c[mt][nt][0], c[mt][nt][1]);
            float2 hi = make_float2(c[mt][nt][2], c[mt][nt][3]);
            *(float2*)&g_part[sp][(size_t)i * 256 + n] = lo;
            *(float2*)&g_part[sp][(size_t)(i + 8) * 256 + n] = hi;
        }
    }
}

// ------------------------------- kernel 3 ----------------------------------
__global__ void gat_k3(float* __restrict__ out) {
    int i = blockIdx.x;
    int c = threadIdx.x;
    float l = g_lpart[0][i] + g_lpart[1][i];
    float hs = g_part[0][i * 256 + c] + g_part[1][i * 256 + c];
    float v = (l > 0.f) ? (hs / l) : 0.f;
    out[i * 256 + c] = (v > 0.f) ? v : (__expf(v) - 1.f);
}

// ------------------------------- launcher ----------------------------------
extern "C" void kernel_launch(void* const* d_in, const int* in_sizes, int n_in,
                              void* d_out, int out_size) {
    const float* h  = (const float*)d_in[0];   // [8192, 512]
    const int* adj  = (const int*)d_in[1];     // [8192, 8192]
    const float* W  = (const float*)d_in[2];   // [512, 256]
    const float* a  = (const float*)d_in[3];   // [512, 1]
    float* out = (float*)d_out;                // [8192, 256]
    (void)in_sizes; (void)n_in; (void)out_size;

    const int SMEM1 = 64512;
    const int SMEM2 = 163840;
    cudaFuncSetAttribute(gat_k1, cudaFuncAttributeMaxDynamicSharedMemorySize, SMEM1);
    cudaFuncSetAttribute(gat_k2, cudaFuncAttributeMaxDynamicSharedMemorySize, SMEM2);

    gat_kp<<<8192, 256>>>(adj);
    gat_k0<<<512, 256>>>(W);
    gat_k0b<<<4, 256>>>(W, a);
    gat_kf<<<1024, 256>>>(h);
    gat_kv<<<32, 256>>>();
    gat_k1<<<128, 256, SMEM1>>>(h);
    gat_k2<<<128, 512, SMEM2>>>();
    gat_k3<<<8192, 256>>>(out);
}